// round 1
// baseline (speedup 1.0000x reference)
#include <cuda_runtime.h>
#include <math.h>

#define BB   2
#define NN   2048
#define DIM  512
#define NH   8
#define KNBR 32
#define PD   16
#define HD   64
#define FF   2048

// ---------------- scratch (static device globals; no allocation) -------------
__device__ float g_xnorm[BB*NN*DIM];
__device__ float g_q[BB*NH*NN*HD];
__device__ float g_k[BB*NH*NN*HD];
__device__ float g_v[BB*NH*NN*HD];
__device__ float g_dist[(size_t)BB*NN*NN];
__device__ int   g_tidx[BB*NN*KNBR];
__device__ float g_tdist[BB*NN*KNBR];
__device__ float g_attn[BB*NN*DIM];
__device__ float g_x1[BB*NN*DIM];
__device__ float g_x2n[BB*NN*DIM];
__device__ float g_h1[(size_t)BB*NN*FF];
__device__ float g_pnsq[BB*NN];

// ---------------- LayerNorm ---------------------------------------------------
__global__ __launch_bounds__(256) void ln_kernel(
    const float* __restrict__ x, const float* __restrict__ scale,
    const float* __restrict__ bias, float* __restrict__ out)
{
    int row = blockIdx.x;
    int tid = threadIdx.x;
    const float* xr = x + (size_t)row * DIM;
    float2 v = ((const float2*)xr)[tid];
    float s  = v.x + v.y;
    float ss = v.x*v.x + v.y*v.y;
    // warp reduce
    for (int o = 16; o; o >>= 1) {
        s  += __shfl_xor_sync(0xffffffffu, s,  o);
        ss += __shfl_xor_sync(0xffffffffu, ss, o);
    }
    __shared__ float sh_s[8], sh_ss[8];
    int warp = tid >> 5, lane = tid & 31;
    if (lane == 0) { sh_s[warp] = s; sh_ss[warp] = ss; }
    __syncthreads();
    float stot = 0.f, sstot = 0.f;
#pragma unroll
    for (int w = 0; w < 8; w++) { stot += sh_s[w]; sstot += sh_ss[w]; }
    float mean = stot * (1.0f / DIM);
    float var  = sstot * (1.0f / DIM) - mean * mean;
    float inv  = rsqrtf(var + 1e-6f);
    float2 sc = ((const float2*)scale)[tid];
    float2 bi = ((const float2*)bias)[tid];
    float2 o2;
    o2.x = (v.x - mean) * inv * sc.x + bi.x;
    o2.y = (v.y - mean) * inv * sc.y + bi.y;
    ((float2*)(out + (size_t)row * DIM))[tid] = o2;
}

// ---------------- SGEMM 128x128x8, 256 thr, 8x8/thread ------------------------
// EPI: 0 = plain (+bias), 1 = heads layout (+bias), 2 = +bias+resid, 3 = gelu(acc+bias)
template<int EPI>
__global__ __launch_bounds__(256) void sgemm(
    const float* __restrict__ A, const float* __restrict__ W,
    const float* __restrict__ bias, const float* __restrict__ resid,
    float* __restrict__ C, int M, int Nd, int Kd)
{
    __shared__ float As[8][128];
    __shared__ float Bs[8][128];
    int tid = threadIdx.x;
    int row0 = blockIdx.y * 128, col0 = blockIdx.x * 128;

    int arow  = tid >> 1;          // 0..127
    int acol4 = (tid & 1) * 4;     // 0 or 4
    int brow  = tid >> 5;          // 0..7
    int bcol4 = (tid & 31) * 4;    // 0..124
    int tx = tid & 15, ty = tid >> 4;

    float acc[8][8];
#pragma unroll
    for (int i = 0; i < 8; i++)
#pragma unroll
        for (int j = 0; j < 8; j++) acc[i][j] = 0.f;

    for (int k0 = 0; k0 < Kd; k0 += 8) {
        float4 av = *(const float4*)(A + (size_t)(row0 + arow) * Kd + k0 + acol4);
        As[acol4 + 0][arow] = av.x;
        As[acol4 + 1][arow] = av.y;
        As[acol4 + 2][arow] = av.z;
        As[acol4 + 3][arow] = av.w;
        float4 bv = *(const float4*)(W + (size_t)(k0 + brow) * Nd + col0 + bcol4);
        *(float4*)&Bs[brow][bcol4] = bv;
        __syncthreads();
#pragma unroll
        for (int kk = 0; kk < 8; kk++) {
            float af[8], bf[8];
            *(float4*)&af[0] = *(const float4*)&As[kk][ty * 8];
            *(float4*)&af[4] = *(const float4*)&As[kk][ty * 8 + 4];
            *(float4*)&bf[0] = *(const float4*)&Bs[kk][tx * 8];
            *(float4*)&bf[4] = *(const float4*)&Bs[kk][tx * 8 + 4];
#pragma unroll
            for (int i = 0; i < 8; i++)
#pragma unroll
                for (int j = 0; j < 8; j++) acc[i][j] += af[i] * bf[j];
        }
        __syncthreads();
    }

#pragma unroll
    for (int i = 0; i < 8; i++) {
        int r = row0 + ty * 8 + i;
#pragma unroll
        for (int j = 0; j < 8; j++) {
            int cc = col0 + tx * 8 + j;
            float val = acc[i][j] + bias[cc];
            if (EPI == 0) {
                C[(size_t)r * Nd + cc] = val;
            } else if (EPI == 1) {
                int b = r / NN, n = r % NN;
                int h = cc / HD, d = cc % HD;
                C[(((size_t)b * NH + h) * NN + n) * HD + d] = val;
            } else if (EPI == 2) {
                C[(size_t)r * Nd + cc] = val + resid[(size_t)r * Nd + cc];
            } else { // gelu (tanh approx)
                float xg = val;
                float t = 0.7978845608028654f * (xg + 0.044715f * xg * xg * xg);
                C[(size_t)r * Nd + cc] = 0.5f * xg * (1.f + tanhf(t));
            }
        }
    }
}

// ---------------- position squared norms --------------------------------------
__global__ void pnsq_kernel(const float* __restrict__ pos)
{
    int r = blockIdx.x * blockDim.x + threadIdx.x;
    if (r < BB * NN) {
        float s = 0.f;
#pragma unroll
        for (int p = 0; p < PD; p++) { float v = pos[(size_t)r * PD + p]; s += v * v; }
        g_pnsq[r] = s;
    }
}

// ---------------- Poincare distance matrix ------------------------------------
__global__ __launch_bounds__(256) void dist_kernel(
    const float* __restrict__ pos, const float* __restrict__ cptr)
{
    int b  = blockIdx.z;
    int i0 = blockIdx.y * 32, j0 = blockIdx.x * 32;
    __shared__ float pi[32][17], pj[32][17];
    __shared__ float ni[32], nj[32];
    int tid = threadIdx.x + threadIdx.y * 32;
    for (int t = tid; t < 512; t += 256) {
        int r = t >> 4, p = t & 15;
        pi[r][p] = pos[((size_t)b * NN + i0 + r) * PD + p];
        pj[r][p] = pos[((size_t)b * NN + j0 + r) * PD + p];
    }
    if (tid < 32) { ni[tid] = g_pnsq[b * NN + i0 + tid]; nj[tid] = g_pnsq[b * NN + j0 + tid]; }
    __syncthreads();
    float c = cptr[0];
    float rsc = rsqrtf(c);
    int j = threadIdx.x;
    float onj = 1.f - c * nj[j];
    for (int iy = threadIdx.y; iy < 32; iy += 8) {
        float ds = 0.f;
#pragma unroll
        for (int p = 0; p < PD; p++) { float d = pi[iy][p] - pj[j][p]; ds += d * d; }
        float den = (1.f - c * ni[iy]) * onj;
        den = fmaxf(den, 1e-8f);
        float arg = 1.f + 2.f * c * ds / den;
        arg = fmaxf(arg, 1.f + 1e-7f);
        g_dist[((size_t)b * NN + (i0 + iy)) * NN + (j0 + j)] = acoshf(arg) * rsc;
    }
}

// ---------------- top-K (smallest distances) per row ---------------------------
__global__ __launch_bounds__(256) void topk_kernel()
{
    const float INF = __int_as_float(0x7f800000);
    int row = blockIdx.x;            // b*NN + i
    int tid = threadIdx.x;
    __shared__ float sd[NN];
    __shared__ float rv[256];
    __shared__ int   ri[256];
    const float* dr = g_dist + (size_t)row * NN;
    for (int t = tid; t < NN; t += 256) sd[t] = dr[t];
    __syncthreads();
    for (int it = 0; it < KNBR; it++) {
        float best = INF; int bi = NN;
        for (int t = tid; t < NN; t += 256) {
            float v = sd[t];
            if (v < best) { best = v; bi = t; }
        }
        rv[tid] = best; ri[tid] = bi;
        __syncthreads();
        for (int s = 128; s > 0; s >>= 1) {
            if (tid < s) {
                float v2 = rv[tid + s]; int i2 = ri[tid + s];
                if (v2 < rv[tid] || (v2 == rv[tid] && i2 < ri[tid])) { rv[tid] = v2; ri[tid] = i2; }
            }
            __syncthreads();
        }
        if (tid == 0) {
            g_tidx [(size_t)row * KNBR + it] = ri[0];
            g_tdist[(size_t)row * KNBR + it] = rv[0];
            sd[ri[0]] = INF;
        }
        __syncthreads();
    }
}

// ---------------- kNN attention (warp per (b,h,i)) ------------------------------
__global__ __launch_bounds__(256) void attn_kernel(
    const float* __restrict__ log_tau, const float* __restrict__ attn_scale)
{
    int warp = threadIdx.x >> 5, lane = threadIdx.x & 31;
    int gw = blockIdx.x * 8 + warp;          // (b*NH+h)*NN + i
    int i  = gw % NN;
    int bh = gw / NN;
    int b  = bh / NH, h = bh % NH;

    __shared__ float qs[8][64];
    __shared__ float ws[8][32];
    __shared__ int   is[8][32];

    const float* qrow = g_q + ((size_t)bh * NN + i) * HD;
    qs[warp][lane]      = qrow[lane];
    qs[warp][lane + 32] = qrow[lane + 32];
    __syncwarp();

    int rowk  = b * NN + i;
    int idx   = g_tidx [(size_t)rowk * KNBR + lane];
    float dj  = g_tdist[(size_t)rowk * KNBR + lane];

    const float* krow = g_k + ((size_t)bh * NN + idx) * HD;
    float dot = 0.f;
#pragma unroll
    for (int d4 = 0; d4 < HD; d4 += 4) {
        float4 kv = *(const float4*)(krow + d4);
        dot += qs[warp][d4] * kv.x + qs[warp][d4 + 1] * kv.y
             + qs[warp][d4 + 2] * kv.z + qs[warp][d4 + 3] * kv.w;
    }
    float tau = fmaxf(expf(log_tau[0]), 1e-8f);
    float s = attn_scale[0] * tanhf(dot * 0.125f - dj / tau);

    float m = s;
    for (int o = 16; o; o >>= 1) m = fmaxf(m, __shfl_xor_sync(0xffffffffu, m, o));
    float e = expf(s - m);
    float sum = e;
    for (int o = 16; o; o >>= 1) sum += __shfl_xor_sync(0xffffffffu, sum, o);
    float w = e / sum;

    ws[warp][lane] = w; is[warp][lane] = idx;
    __syncwarp();

    float a0 = 0.f, a1 = 0.f;
#pragma unroll
    for (int j = 0; j < KNBR; j++) {
        const float* vrow = g_v + ((size_t)bh * NN + is[warp][j]) * HD;
        float wj = ws[warp][j];
        a0 += wj * vrow[lane];
        a1 += wj * vrow[lane + 32];
    }
    float* orow = g_attn + ((size_t)(b * NN + i)) * DIM + h * HD;
    orow[lane]      = a0;
    orow[lane + 32] = a1;
}

// ---------------- launch -------------------------------------------------------
extern "C" void kernel_launch(void* const* d_in, const int* in_sizes, int n_in,
                              void* d_out, int out_size)
{
    const float* x        = (const float*)d_in[0];
    const float* pos      = (const float*)d_in[1];
    const float* c        = (const float*)d_in[2];
    const float* Wq = (const float*)d_in[3];  const float* bq = (const float*)d_in[4];
    const float* Wk = (const float*)d_in[5];  const float* bk = (const float*)d_in[6];
    const float* Wv = (const float*)d_in[7];  const float* bv = (const float*)d_in[8];
    const float* Wo = (const float*)d_in[9];  const float* bo = (const float*)d_in[10];
    const float* W1 = (const float*)d_in[11]; const float* b1 = (const float*)d_in[12];
    const float* W2 = (const float*)d_in[13]; const float* b2 = (const float*)d_in[14];
    const float* ln1s = (const float*)d_in[15]; const float* ln1b = (const float*)d_in[16];
    const float* ln2s = (const float*)d_in[17]; const float* ln2b = (const float*)d_in[18];
    const float* log_tau    = (const float*)d_in[19];
    const float* attn_scale = (const float*)d_in[20];
    float* out = (float*)d_out;

    float *p_xnorm, *p_q, *p_k, *p_v, *p_attn, *p_x1, *p_x2n, *p_h1;
    cudaGetSymbolAddress((void**)&p_xnorm, g_xnorm);
    cudaGetSymbolAddress((void**)&p_q, g_q);
    cudaGetSymbolAddress((void**)&p_k, g_k);
    cudaGetSymbolAddress((void**)&p_v, g_v);
    cudaGetSymbolAddress((void**)&p_attn, g_attn);
    cudaGetSymbolAddress((void**)&p_x1, g_x1);
    cudaGetSymbolAddress((void**)&p_x2n, g_x2n);
    cudaGetSymbolAddress((void**)&p_h1, g_h1);

    const int M = BB * NN;   // 4096

    // 1. LN1
    ln_kernel<<<M, 256>>>(x, ln1s, ln1b, p_xnorm);

    // 2. QKV projections (heads layout epilogue)
    dim3 g512(DIM / 128, M / 128);
    sgemm<1><<<g512, 256>>>(p_xnorm, Wq, bq, nullptr, p_q, M, DIM, DIM);
    sgemm<1><<<g512, 256>>>(p_xnorm, Wk, bk, nullptr, p_k, M, DIM, DIM);
    sgemm<1><<<g512, 256>>>(p_xnorm, Wv, bv, nullptr, p_v, M, DIM, DIM);

    // 3. distances + top-k
    pnsq_kernel<<<(BB * NN + 255) / 256, 256>>>(pos);
    dist_kernel<<<dim3(NN / 32, NN / 32, BB), dim3(32, 8)>>>(pos, c);
    topk_kernel<<<BB * NN, 256>>>();

    // 4. attention
    attn_kernel<<<BB * NH * NN / 8, 256>>>(log_tau, attn_scale);

    // 5. output projection + residual
    sgemm<2><<<g512, 256>>>(p_attn, Wo, bo, x, p_x1, M, DIM, DIM);

    // 6. LN2
    ln_kernel<<<M, 256>>>(p_x1, ln2s, ln2b, p_x2n);

    // 7. FFN
    dim3 gff1(FF / 128, M / 128);
    sgemm<3><<<gff1, 256>>>(p_x2n, W1, b1, nullptr, p_h1, M, FF, DIM);
    sgemm<2><<<g512, 256>>>(p_h1, W2, b2, p_x1, out, M, DIM, FF);
}

// round 8
// speedup vs baseline: 2.3462x; 2.3462x over previous
#include <cuda_runtime.h>
#include <math.h>
#include <stdint.h>

#define BB   2
#define NN   2048
#define DIM  512
#define NH   8
#define KNBR 32
#define PD   16
#define HD   64
#define FF   2048

// ======================= helpers =============================================
__device__ __forceinline__ uint32_t smem_u32(const void* p) {
    uint32_t a;
    asm("{ .reg .u64 t; cvta.to.shared.u64 t, %1; cvt.u32.u64 %0, t; }"
        : "=r"(a) : "l"(p));
    return a;
}

__device__ __forceinline__ float rtf32(float x) {
    uint32_t u;
    asm("cvt.rna.tf32.f32 %0, %1;" : "=r"(u) : "f"(x));
    return __uint_as_float(u);
}

// ======================= scratch =============================================
__device__ float g_xnorm[BB*NN*DIM];
__device__ float g_q[BB*NH*NN*HD];
__device__ float g_k[BB*NH*NN*HD];
__device__ float g_v[BB*NH*NN*HD];
__device__ float g_dist[(size_t)BB*NN*NN];
__device__ int   g_tidx[BB*NN*KNBR];
__device__ float g_tdist[BB*NN*KNBR];
__device__ float g_attn[BB*NN*DIM];
__device__ float g_x1[BB*NN*DIM];
__device__ float g_x2n[BB*NN*DIM];
__device__ float g_h1[(size_t)BB*NN*FF];
__device__ float g_pnsq[BB*NN];
// transposed (N,K) tf32-rounded weights
__device__ float g_wqt[DIM*DIM];
__device__ float g_wkt[DIM*DIM];
__device__ float g_wvt[DIM*DIM];
__device__ float g_wot[DIM*DIM];
__device__ float g_w1t[FF*DIM];
__device__ float g_w2t[DIM*FF];

// ======================= weight transpose (+tf32 round) ======================
__global__ __launch_bounds__(256) void transpose_w(
    const float* __restrict__ in, float* __restrict__ out, int R, int C)
{
    __shared__ float t[32][33];
    int c0 = blockIdx.x * 32, r0 = blockIdx.y * 32;
    int x = threadIdx.x, y = threadIdx.y;
#pragma unroll
    for (int dy = 0; dy < 32; dy += 8)
        t[y + dy][x] = in[(size_t)(r0 + y + dy) * C + c0 + x];
    __syncthreads();
#pragma unroll
    for (int dy = 0; dy < 32; dy += 8)
        out[(size_t)(c0 + y + dy) * R + r0 + x] = rtf32(t[x][y + dy]);
}

// ======================= mma.sync tf32 GEMM ==================================
// C[M,Nd] = A[M,Kd] @ Bt[Nd,Kd]^T + epilogue
// EPI: 1 = heads layout (+bias), 2 = +bias+resid, 3 = gelu(acc+bias) -> tf32
// Tiles: CTA 128x128, BK=32, 4-stage cp.async, 8 warps of 32x64.

#define SA 36                      // padded row stride (floats)
#define STAGE_FLOATS (2 * 128 * SA)  // A tile + B tile = 9216
#define SMEM_FLOATS  (4 * STAGE_FLOATS)

__device__ __forceinline__ void issue_tile(
    const float* __restrict__ A, const float* __restrict__ Bt,
    float* sm, int row0, int col0, int Kd, int t, int tid)
{
    float* as = sm + (t & 3) * STAGE_FLOATS;
    float* bs = as + 128 * SA;
    int k0 = t * 32;
#pragma unroll
    for (int it = 0; it < 4; it++) {
        int cch = tid + it * 256;            // 0..1023
        int r = cch >> 3, k4 = (cch & 7) * 4;
        uint32_t da = smem_u32(as + r * SA + k4);
        const float* ga = A + (size_t)(row0 + r) * Kd + k0 + k4;
        asm volatile("cp.async.cg.shared.global [%0], [%1], 16;" :: "r"(da), "l"(ga));
        uint32_t db = smem_u32(bs + r * SA + k4);
        const float* gb = Bt + (size_t)(col0 + r) * Kd + k0 + k4;
        asm volatile("cp.async.cg.shared.global [%0], [%1], 16;" :: "r"(db), "l"(gb));
    }
    asm volatile("cp.async.commit_group;" ::: "memory");
}

template<int EPI>
__global__ __launch_bounds__(256) void mma_gemm(
    const float* __restrict__ A, const float* __restrict__ Bt,
    const float* __restrict__ bias, const float* __restrict__ resid,
    float* __restrict__ C, int M, int Nd, int Kd)
{
    extern __shared__ __align__(16) float sm[];
    int tid = threadIdx.x, wid = tid >> 5, lane = tid & 31;
    int g = lane >> 2, tig = lane & 3;
    int row0 = blockIdx.y * 128, col0 = blockIdx.x * 128;
    int m0 = (wid & 3) * 32, n0 = (wid >> 2) * 64;

    float acc[2][8][4];
#pragma unroll
    for (int mt = 0; mt < 2; mt++)
#pragma unroll
        for (int nt = 0; nt < 8; nt++)
#pragma unroll
            for (int u = 0; u < 4; u++) acc[mt][nt][u] = 0.f;

    const int tiles = Kd >> 5;
    issue_tile(A, Bt, sm, row0, col0, Kd, 0, tid);
    issue_tile(A, Bt, sm, row0, col0, Kd, 1, tid);

    for (int t = 0; t < tiles; t++) {
        if (t + 2 < tiles) issue_tile(A, Bt, sm, row0, col0, Kd, t + 2, tid);
        int rem = tiles - 1 - t;
        if (rem >= 2)      asm volatile("cp.async.wait_group 2;" ::: "memory");
        else if (rem == 1) asm volatile("cp.async.wait_group 1;" ::: "memory");
        else               asm volatile("cp.async.wait_group 0;" ::: "memory");
        __syncthreads();

        const float* as = sm + (t & 3) * STAGE_FLOATS;
        const float* bs = as + 128 * SA;
#pragma unroll
        for (int kk = 0; kk < 32; kk += 8) {
            uint32_t a[2][4];
#pragma unroll
            for (int mt = 0; mt < 2; mt++) {
                const float* ar0 = as + (m0 + mt * 16 + g) * SA + kk;
                const float* ar1 = as + (m0 + mt * 16 + g + 8) * SA + kk;
                a[mt][0] = __float_as_uint(ar0[tig]);
                a[mt][1] = __float_as_uint(ar1[tig]);
                a[mt][2] = __float_as_uint(ar0[tig + 4]);
                a[mt][3] = __float_as_uint(ar1[tig + 4]);
            }
            uint32_t b[8][2];
#pragma unroll
            for (int nt = 0; nt < 8; nt++) {
                const float* br = bs + (n0 + nt * 8 + g) * SA + kk;
                b[nt][0] = __float_as_uint(br[tig]);
                b[nt][1] = __float_as_uint(br[tig + 4]);
            }
#pragma unroll
            for (int mt = 0; mt < 2; mt++)
#pragma unroll
                for (int nt = 0; nt < 8; nt++)
                    asm volatile(
                        "mma.sync.aligned.m16n8k8.row.col.f32.tf32.tf32.f32 "
                        "{%0,%1,%2,%3}, {%4,%5,%6,%7}, {%8,%9}, {%0,%1,%2,%3};"
                        : "+f"(acc[mt][nt][0]), "+f"(acc[mt][nt][1]),
                          "+f"(acc[mt][nt][2]), "+f"(acc[mt][nt][3])
                        : "r"(a[mt][0]), "r"(a[mt][1]), "r"(a[mt][2]), "r"(a[mt][3]),
                          "r"(b[nt][0]), "r"(b[nt][1]));
        }
    }

    // ---- epilogue straight from registers ----
#pragma unroll
    for (int mt = 0; mt < 2; mt++) {
        int ra = row0 + m0 + mt * 16 + g;      // rows ra and ra+8
#pragma unroll
        for (int nt = 0; nt < 8; nt++) {
            int cc = col0 + n0 + nt * 8 + tig * 2;
            float b0 = bias[cc], b1 = bias[cc + 1];
            float v0 = acc[mt][nt][0] + b0, v1 = acc[mt][nt][1] + b1;
            float v2 = acc[mt][nt][2] + b0, v3 = acc[mt][nt][3] + b1;

            if (EPI == 1) {
                int h = cc >> 6, d0 = cc & 63;
                int bb0 = ra >> 11, n_0 = ra & (NN - 1);
                int bb1 = (ra + 8) >> 11, n_1 = (ra + 8) & (NN - 1);
                float* p0 = g_q; // placeholder (unused)
                (void)p0;
                float* d0p = C + (((size_t)bb0 * NH + h) * NN + n_0) * HD + d0;
                float* d1p = C + (((size_t)bb1 * NH + h) * NN + n_1) * HD + d0;
                *(float2*)d0p = make_float2(v0, v1);
                *(float2*)d1p = make_float2(v2, v3);
            } else if (EPI == 2) {
                float* p0 = C + (size_t)ra * Nd + cc;
                float* p1 = C + (size_t)(ra + 8) * Nd + cc;
                const float* r0p = resid + (size_t)ra * Nd + cc;
                const float* r1p = resid + (size_t)(ra + 8) * Nd + cc;
                float2 rv0 = *(const float2*)r0p;
                float2 rv1 = *(const float2*)r1p;
                *(float2*)p0 = make_float2(v0 + rv0.x, v1 + rv0.y);
                *(float2*)p1 = make_float2(v2 + rv1.x, v3 + rv1.y);
            } else { // gelu -> tf32
                float vv[4] = {v0, v1, v2, v3};
#pragma unroll
                for (int u = 0; u < 4; u++) {
                    float xg = vv[u];
                    float tt = 0.7978845608028654f * (xg + 0.044715f * xg * xg * xg);
                    vv[u] = rtf32(0.5f * xg * (1.f + tanhf(tt)));
                }
                float* p0 = C + (size_t)ra * Nd + cc;
                float* p1 = C + (size_t)(ra + 8) * Nd + cc;
                *(float2*)p0 = make_float2(vv[0], vv[1]);
                *(float2*)p1 = make_float2(vv[2], vv[3]);
            }
        }
    }
}

// ======================= LayerNorm (tf32-rounded output) =====================
__global__ __launch_bounds__(256) void ln_kernel(
    const float* __restrict__ x, const float* __restrict__ scale,
    const float* __restrict__ bias, float* __restrict__ out)
{
    int row = blockIdx.x;
    int tid = threadIdx.x;
    const float* xr = x + (size_t)row * DIM;
    float2 v = ((const float2*)xr)[tid];
    float s  = v.x + v.y;
    float ss = v.x*v.x + v.y*v.y;
    for (int o = 16; o; o >>= 1) {
        s  += __shfl_xor_sync(0xffffffffu, s,  o);
        ss += __shfl_xor_sync(0xffffffffu, ss, o);
    }
    __shared__ float sh_s[8], sh_ss[8];
    int warp = tid >> 5, lane = tid & 31;
    if (lane == 0) { sh_s[warp] = s; sh_ss[warp] = ss; }
    __syncthreads();
    float stot = 0.f, sstot = 0.f;
#pragma unroll
    for (int w = 0; w < 8; w++) { stot += sh_s[w]; sstot += sh_ss[w]; }
    float mean = stot * (1.0f / DIM);
    float var  = sstot * (1.0f / DIM) - mean * mean;
    float inv  = rsqrtf(var + 1e-6f);
    float2 sc = ((const float2*)scale)[tid];
    float2 bi = ((const float2*)bias)[tid];
    float2 o2;
    o2.x = rtf32((v.x - mean) * inv * sc.x + bi.x);
    o2.y = rtf32((v.y - mean) * inv * sc.y + bi.y);
    ((float2*)(out + (size_t)row * DIM))[tid] = o2;
}

// ======================= position squared norms ==============================
__global__ void pnsq_kernel(const float* __restrict__ pos)
{
    int r = blockIdx.x * blockDim.x + threadIdx.x;
    if (r < BB * NN) {
        float s = 0.f;
#pragma unroll
        for (int p = 0; p < PD; p++) { float v = pos[(size_t)r * PD + p]; s += v * v; }
        g_pnsq[r] = s;
    }
}

// ======================= Poincare distance matrix ============================
__global__ __launch_bounds__(256) void dist_kernel(
    const float* __restrict__ pos, const float* __restrict__ cptr)
{
    int b  = blockIdx.z;
    int i0 = blockIdx.y * 32, j0 = blockIdx.x * 32;
    __shared__ float pi[32][17], pj[32][17];
    __shared__ float ni[32], nj[32];
    int tid = threadIdx.x + threadIdx.y * 32;
    for (int t = tid; t < 512; t += 256) {
        int r = t >> 4, p = t & 15;
        pi[r][p] = pos[((size_t)b * NN + i0 + r) * PD + p];
        pj[r][p] = pos[((size_t)b * NN + j0 + r) * PD + p];
    }
    if (tid < 32) { ni[tid] = g_pnsq[b * NN + i0 + tid]; nj[tid] = g_pnsq[b * NN + j0 + tid]; }
    __syncthreads();
    float c = cptr[0];
    float rsc = rsqrtf(c);
    int j = threadIdx.x;
    float onj = 1.f - c * nj[j];
    for (int iy = threadIdx.y; iy < 32; iy += 8) {
        float ds = 0.f;
#pragma unroll
        for (int p = 0; p < PD; p++) { float d = pi[iy][p] - pj[j][p]; ds += d * d; }
        float den = (1.f - c * ni[iy]) * onj;
        den = fmaxf(den, 1e-8f);
        float arg = 1.f + 2.f * c * ds / den;
        arg = fmaxf(arg, 1.f + 1e-7f);
        g_dist[((size_t)b * NN + (i0 + iy)) * NN + (j0 + j)] = acoshf(arg) * rsc;
    }
}

// ======================= top-K per row =======================================
__global__ __launch_bounds__(256) void topk_kernel()
{
    const float INF = __int_as_float(0x7f800000);
    int row = blockIdx.x;
    int tid = threadIdx.x;
    __shared__ float sd[NN];
    __shared__ float rv[256];
    __shared__ int   ri[256];
    const float* dr = g_dist + (size_t)row * NN;
    for (int t = tid; t < NN; t += 256) sd[t] = dr[t];
    __syncthreads();
    for (int it = 0; it < KNBR; it++) {
        float best = INF; int bi = NN;
        for (int t = tid; t < NN; t += 256) {
            float v = sd[t];
            if (v < best) { best = v; bi = t; }
        }
        rv[tid] = best; ri[tid] = bi;
        __syncthreads();
        for (int s = 128; s > 0; s >>= 1) {
            if (tid < s) {
                float v2 = rv[tid + s]; int i2 = ri[tid + s];
                if (v2 < rv[tid] || (v2 == rv[tid] && i2 < ri[tid])) { rv[tid] = v2; ri[tid] = i2; }
            }
            __syncthreads();
        }
        if (tid == 0) {
            g_tidx [(size_t)row * KNBR + it] = ri[0];
            g_tdist[(size_t)row * KNBR + it] = rv[0];
            sd[ri[0]] = INF;
        }
        __syncthreads();
    }
}

// ======================= kNN attention (warp per (b,h,i)) ====================
__global__ __launch_bounds__(256) void attn_kernel(
    const float* __restrict__ log_tau, const float* __restrict__ attn_scale)
{
    int warp = threadIdx.x >> 5, lane = threadIdx.x & 31;
    int gw = blockIdx.x * 8 + warp;
    int i  = gw % NN;
    int bh = gw / NN;
    int b  = bh / NH, h = bh % NH;

    __shared__ float qs[8][64];
    __shared__ float ws[8][32];
    __shared__ int   is[8][32];

    const float* qrow = g_q + ((size_t)bh * NN + i) * HD;
    qs[warp][lane]      = qrow[lane];
    qs[warp][lane + 32] = qrow[lane + 32];
    __syncwarp();

    int rowk  = b * NN + i;
    int idx   = g_tidx [(size_t)rowk * KNBR + lane];
    float dj  = g_tdist[(size_t)rowk * KNBR + lane];

    const float* krow = g_k + ((size_t)bh * NN + idx) * HD;
    float dot = 0.f;
#pragma unroll
    for (int d4 = 0; d4 < HD; d4 += 4) {
        float4 kv = *(const float4*)(krow + d4);
        dot += qs[warp][d4] * kv.x + qs[warp][d4 + 1] * kv.y
             + qs[warp][d4 + 2] * kv.z + qs[warp][d4 + 3] * kv.w;
    }
    float tau = fmaxf(expf(log_tau[0]), 1e-8f);
    float s = attn_scale[0] * tanhf(dot * 0.125f - dj / tau);

    float m = s;
    for (int o = 16; o; o >>= 1) m = fmaxf(m, __shfl_xor_sync(0xffffffffu, m, o));
    float e = expf(s - m);
    float sum = e;
    for (int o = 16; o; o >>= 1) sum += __shfl_xor_sync(0xffffffffu, sum, o);
    float w = e / sum;

    ws[warp][lane] = w; is[warp][lane] = idx;
    __syncwarp();

    float a0 = 0.f, a1 = 0.f;
#pragma unroll
    for (int j = 0; j < KNBR; j++) {
        const float* vrow = g_v + ((size_t)bh * NN + is[warp][j]) * HD;
        float wj = ws[warp][j];
        a0 += wj * vrow[lane];
        a1 += wj * vrow[lane + 32];
    }
    float* orow = g_attn + ((size_t)(b * NN + i)) * DIM + h * HD;
    orow[lane]      = rtf32(a0);
    orow[lane + 32] = rtf32(a1);
}

// ======================= launch ==============================================
extern "C" void kernel_launch(void* const* d_in, const int* in_sizes, int n_in,
                              void* d_out, int out_size)
{
    const float* x        = (const float*)d_in[0];
    const float* pos      = (const float*)d_in[1];
    const float* c        = (const float*)d_in[2];
    const float* Wq = (const float*)d_in[3];  const float* bq = (const float*)d_in[4];
    const float* Wk = (const float*)d_in[5];  const float* bk = (const float*)d_in[6];
    const float* Wv = (const float*)d_in[7];  const float* bv = (const float*)d_in[8];
    const float* Wo = (const float*)d_in[9];  const float* bo = (const float*)d_in[10];
    const float* W1 = (const float*)d_in[11]; const float* b1 = (const float*)d_in[12];
    const float* W2 = (const float*)d_in[13]; const float* b2 = (const float*)d_in[14];
    const float* ln1s = (const float*)d_in[15]; const float* ln1b = (const float*)d_in[16];
    const float* ln2s = (const float*)d_in[17]; const float* ln2b = (const float*)d_in[18];
    const float* log_tau    = (const float*)d_in[19];
    const float* attn_scale = (const float*)d_in[20];
    float* out = (float*)d_out;

    float *p_xnorm, *p_q, *p_k, *p_v, *p_attn, *p_x1, *p_x2n, *p_h1;
    float *p_wqt, *p_wkt, *p_wvt, *p_wot, *p_w1t, *p_w2t;
    cudaGetSymbolAddress((void**)&p_xnorm, g_xnorm);
    cudaGetSymbolAddress((void**)&p_q, g_q);
    cudaGetSymbolAddress((void**)&p_k, g_k);
    cudaGetSymbolAddress((void**)&p_v, g_v);
    cudaGetSymbolAddress((void**)&p_attn, g_attn);
    cudaGetSymbolAddress((void**)&p_x1, g_x1);
    cudaGetSymbolAddress((void**)&p_x2n, g_x2n);
    cudaGetSymbolAddress((void**)&p_h1, g_h1);
    cudaGetSymbolAddress((void**)&p_wqt, g_wqt);
    cudaGetSymbolAddress((void**)&p_wkt, g_wkt);
    cudaGetSymbolAddress((void**)&p_wvt, g_wvt);
    cudaGetSymbolAddress((void**)&p_wot, g_wot);
    cudaGetSymbolAddress((void**)&p_w1t, g_w1t);
    cudaGetSymbolAddress((void**)&p_w2t, g_w2t);

    const int SMEM_BYTES = SMEM_FLOATS * 4;   // 147456
    cudaFuncSetAttribute(mma_gemm<1>, cudaFuncAttributeMaxDynamicSharedMemorySize, SMEM_BYTES);
    cudaFuncSetAttribute(mma_gemm<2>, cudaFuncAttributeMaxDynamicSharedMemorySize, SMEM_BYTES);
    cudaFuncSetAttribute(mma_gemm<3>, cudaFuncAttributeMaxDynamicSharedMemorySize, SMEM_BYTES);

    const int M = BB * NN;   // 4096
    dim3 tb(32, 8);

    // weight transposes ([K,N] -> [N,K], tf32-rounded)
    transpose_w<<<dim3(DIM/32, DIM/32), tb>>>(Wq, p_wqt, DIM, DIM);
    transpose_w<<<dim3(DIM/32, DIM/32), tb>>>(Wk, p_wkt, DIM, DIM);
    transpose_w<<<dim3(DIM/32, DIM/32), tb>>>(Wv, p_wvt, DIM, DIM);
    transpose_w<<<dim3(DIM/32, DIM/32), tb>>>(Wo, p_wot, DIM, DIM);
    transpose_w<<<dim3(FF/32,  DIM/32), tb>>>(W1, p_w1t, DIM, FF);
    transpose_w<<<dim3(DIM/32, FF/32),  tb>>>(W2, p_w2t, FF, DIM);

    // 1. LN1
    ln_kernel<<<M, 256>>>(x, ln1s, ln1b, p_xnorm);

    // 2. QKV projections (heads layout epilogue)
    dim3 g512(DIM / 128, M / 128);
    mma_gemm<1><<<g512, 256, SMEM_BYTES>>>(p_xnorm, p_wqt, bq, nullptr, p_q, M, DIM, DIM);
    mma_gemm<1><<<g512, 256, SMEM_BYTES>>>(p_xnorm, p_wkt, bk, nullptr, p_k, M, DIM, DIM);
    mma_gemm<1><<<g512, 256, SMEM_BYTES>>>(p_xnorm, p_wvt, bv, nullptr, p_v, M, DIM, DIM);

    // 3. distances + top-k
    pnsq_kernel<<<(BB * NN + 255) / 256, 256>>>(pos);
    dist_kernel<<<dim3(NN / 32, NN / 32, BB), dim3(32, 8)>>>(pos, c);
    topk_kernel<<<BB * NN, 256>>>();

    // 4. attention
    attn_kernel<<<BB * NH * NN / 8, 256>>>(log_tau, attn_scale);

    // 5. output projection + residual
    mma_gemm<2><<<g512, 256, SMEM_BYTES>>>(p_attn, p_wot, bo, x, p_x1, M, DIM, DIM);

    // 6. LN2
    ln_kernel<<<M, 256>>>(p_x1, ln2s, ln2b, p_x2n);

    // 7. FFN
    dim3 gff1(FF / 128, M / 128);
    mma_gemm<3><<<gff1, 256, SMEM_BYTES>>>(p_x2n, p_w1t, b1, nullptr, p_h1, M, FF, DIM);
    mma_gemm<2><<<g512, 256, SMEM_BYTES>>>(p_h1, p_w2t, b2, p_x1, out, M, DIM, FF);
}